// round 8
// baseline (speedup 1.0000x reference)
#include <cuda_runtime.h>
#include <cuda_bf16.h>
#include <cstdint>
#include <math.h>

#define NQ      32768
#define KC      8192
#define DD      256
#define MT      128           // queries per CTA
#define NTILE   128           // codes per tile
#define NTILES  (KC / NTILE)  // 64
#define NSTAGES (NTILES * 4)  // 256 (64-dim chunks)
#define EPS     2e-6f

// ---------------- device scratch (no cudaMalloc) ----------------------------
__device__ float         g_cbsq[KC];
__device__ __nv_bfloat16 g_cb_hi[KC * DD];
__device__ __nv_bfloat16 g_cb_lo[KC * DD];
__device__ float         g_gap[NQ];

// ---------------- smem layout (bytes) ---------------------------------------
// A: 4 dc-chunks x (128 x 64 bf16 SW128) = 64KB hi + 64KB lo
// B: 3 stages x (hi 16KB + lo 16KB) = 96KB
// reductions overlay the B region after the mainloop.
#define SM_A_HI  0
#define SM_A_LO  65536
#define SM_B     131072
#define SM_TOTAL 229376        // 224 KB

__device__ __forceinline__ uint32_t smem_u32(const void* p) {
    uint32_t a;
    asm("{ .reg .u64 t; cvta.to.shared.u64 t, %1; cvt.u32.u64 %0, t; }"
        : "=r"(a) : "l"(p));
    return a;
}
__device__ __forceinline__ uint32_t swz(uint32_t b) { return b ^ ((b >> 3) & 0x70); }

#define LDSM_X4(r0, r1, r2, r3, addr) \
    asm volatile("ldmatrix.sync.aligned.m8n8.x4.shared.b16 {%0,%1,%2,%3}, [%4];" \
                 : "=r"(r0), "=r"(r1), "=r"(r2), "=r"(r3) : "r"(addr))

#define MMA_BF16(c0, c1, c2, c3, a0, a1, a2, a3, b0, b1) \
    asm volatile("mma.sync.aligned.m16n8k16.row.col.f32.bf16.bf16.f32 " \
                 "{%0,%1,%2,%3}, {%4,%5,%6,%7}, {%8,%9}, {%0,%1,%2,%3};" \
                 : "+f"(c0), "+f"(c1), "+f"(c2), "+f"(c3) \
                 : "r"(a0), "r"(a1), "r"(a2), "r"(a3), "r"(b0), "r"(b1))

#define CP16(dst, src) \
    asm volatile("cp.async.cg.shared.global [%0], [%1], 16;" :: "r"(dst), "l"(src))
#define CP_COMMIT() asm volatile("cp.async.commit_group;" ::: "memory")
#define CP_WAIT(n)  asm volatile("cp.async.wait_group %0;" :: "n"(n) : "memory")

// ---------------------------------------------------------------------------
// Prep: split codebook to bf16 hi/lo + ||e||^2. One warp per code.
// ---------------------------------------------------------------------------
__global__ void prep_kernel(const float* __restrict__ cb) {
    int w = (blockIdx.x * blockDim.x + threadIdx.x) >> 5;
    int lane = threadIdx.x & 31;
    if (w >= KC) return;
    const float4* row = (const float4*)(cb + (size_t)w * DD);
    float s = 0.f;
    #pragma unroll
    for (int i = 0; i < 2; i++) {
        int f = lane + i * 32;
        float4 v = row[f];
        s += v.x * v.x + v.y * v.y + v.z * v.z + v.w * v.w;
        float xs[4] = {v.x, v.y, v.z, v.w};
        __nv_bfloat16 h[4], l[4];
        #pragma unroll
        for (int j = 0; j < 4; j++) {
            h[j] = __float2bfloat16_rn(xs[j]);
            l[j] = __float2bfloat16_rn(xs[j] - __bfloat162float(h[j]));
        }
        __nv_bfloat162 h0 = {h[0], h[1]}, h1 = {h[2], h[3]};
        __nv_bfloat162 l0 = {l[0], l[1]}, l1 = {l[2], l[3]};
        uint2 hu = {*(uint32_t*)&h0, *(uint32_t*)&h1};
        uint2 lu = {*(uint32_t*)&l0, *(uint32_t*)&l1};
        *(uint2*)(g_cb_hi + (size_t)w * DD + f * 4) = hu;
        *(uint2*)(g_cb_lo + (size_t)w * DD + f * 4) = lu;
    }
    #pragma unroll
    for (int off = 16; off; off >>= 1) s += __shfl_xor_sync(0xffffffffu, s, off);
    if (lane == 0) g_cbsq[w] = s;
}

// ---------------------------------------------------------------------------
// Main: HMMA bf16x3 GEMM + fused top-2 argmin.
// 512 threads = 16 warps (4M x 4N). CTA: 128 queries x all 8192 codes.
// 3-stage cp.async pipeline, ONE __syncthreads per 64-dim stage.
// ---------------------------------------------------------------------------
__global__ void __launch_bounds__(512, 1)
vq_mma_kernel(const float* __restrict__ z, float* __restrict__ out) {
    extern __shared__ char smem[];
    const uint32_t sb = smem_u32(smem);
    const int tid  = threadIdx.x;
    const int wid  = tid >> 5;
    const int lane = tid & 31;
    const int wm   = wid >> 2;     // 0..3
    const int wn   = wid & 3;      // 0..3
    const int qbase = blockIdx.x * MT;

    // per-thread cp.async source/dest components (same for every stage)
    const int cp_row0 = tid >> 3;            // rows 0..63  (chunk i=0)
    const int cp_row1 = (tid + 512) >> 3;    // rows 64..127 (chunk i=1)
    const int cp_c8   = (tid & 7) * 8;
    const uint32_t cp_o0 = swz((uint32_t)(cp_row0 * 128 + cp_c8 * 2));
    const uint32_t cp_o1 = swz((uint32_t)(cp_row1 * 128 + cp_c8 * 2));

    // ---- prologue: issue B stages 0 and 1 -----------------------------------
    #pragma unroll
    for (int s = 0; s < 2; s++) {
        const uint32_t bst = sb + SM_B + s * 32768;
        const int tile = s >> 2, dc = s & 3;
        size_t src0 = (size_t)(tile * NTILE + cp_row0) * DD + dc * 64 + cp_c8;
        size_t src1 = (size_t)(tile * NTILE + cp_row1) * DD + dc * 64 + cp_c8;
        CP16(bst + cp_o0,         g_cb_hi + src0);
        CP16(bst + 16384 + cp_o0, g_cb_lo + src0);
        CP16(bst + cp_o1,         g_cb_hi + src1);
        CP16(bst + 16384 + cp_o1, g_cb_lo + src1);
        CP_COMMIT();
    }

    // ---- convert z tile (128x256 fp32) to swizzled hi/lo bf16 chunks --------
    #pragma unroll
    for (int i = 0; i < 16; i++) {
        int id  = tid + i * 512;           // float4 id, 8192 total
        int row = id >> 6;
        int col = (id & 63) * 4;           // bf16 col 0..252
        int dc  = col >> 6;
        int cl  = col & 63;
        float4 v = *(const float4*)(z + (size_t)(qbase + row) * DD + col);
        float xs[4] = {v.x, v.y, v.z, v.w};
        __nv_bfloat16 h[4], l[4];
        #pragma unroll
        for (int j = 0; j < 4; j++) {
            h[j] = __float2bfloat16_rn(xs[j]);
            l[j] = __float2bfloat16_rn(xs[j] - __bfloat162float(h[j]));
        }
        __nv_bfloat162 h0 = {h[0], h[1]}, h1 = {h[2], h[3]};
        __nv_bfloat162 l0 = {l[0], l[1]}, l1 = {l[2], l[3]};
        uint2 hu = {*(uint32_t*)&h0, *(uint32_t*)&h1};
        uint2 lu = {*(uint32_t*)&l0, *(uint32_t*)&l1};
        uint32_t o = (uint32_t)(dc * 16384) + swz((uint32_t)(row * 128 + cl * 2));
        *(uint2*)(smem + SM_A_HI + o) = hu;
        *(uint2*)(smem + SM_A_LO + o) = lu;
    }

    // lane-derived fragment address components (validated in R6/R7)
    const int a_r  = wm * 32 + (lane & 15);
    const int a_c8 = (lane >> 4) * 8;
    const int b_r  = wn * 32 + (lane & 7) + ((lane >> 4) & 1) * 8;
    const int b_c8 = ((lane >> 3) & 1) * 8;

    float t1d[4], t2d[4];
    int   t1i[4];
    #pragma unroll
    for (int s = 0; s < 4; s++) { t1d[s] = INFINITY; t2d[s] = INFINITY; t1i[s] = 0x7fffffff; }

    float acc[2][4][4] = {};

    #pragma unroll 1
    for (int s = 0; s < NSTAGES; s++) {
        const int tile = s >> 2;
        const int dc   = s & 3;
        const uint32_t buf = sb + SM_B + (uint32_t)(s % 3) * 32768;

        if (s + 1 < NSTAGES) { CP_WAIT(1); } else { CP_WAIT(0); }
        __syncthreads();   // stage s visible; buffer (s+2)%3 free (read at s-1)

        // issue stage s+2
        if (s + 2 < NSTAGES) {
            const int nt_ = (s + 2) >> 2, ndc = (s + 2) & 3;
            const uint32_t bst = sb + SM_B + (uint32_t)((s + 2) % 3) * 32768;
            size_t src0 = (size_t)(nt_ * NTILE + cp_row0) * DD + ndc * 64 + cp_c8;
            size_t src1 = (size_t)(nt_ * NTILE + cp_row1) * DD + ndc * 64 + cp_c8;
            CP16(bst + cp_o0,         g_cb_hi + src0);
            CP16(bst + 16384 + cp_o0, g_cb_lo + src0);
            CP16(bst + cp_o1,         g_cb_hi + src1);
            CP16(bst + 16384 + cp_o1, g_cb_lo + src1);
            CP_COMMIT();
        }

        const uint32_t a_hi_base = sb + SM_A_HI + dc * 16384;
        const uint32_t a_lo_base = sb + SM_A_LO + dc * 16384;
        const uint32_t b_hi_base = buf;
        const uint32_t b_lo_base = buf + 16384;

        #pragma unroll
        for (int k16 = 0; k16 < 4; k16++) {
            const int kc = k16 * 16;
            uint32_t ah[2][4], al[2][4], fh[2][4], fl[2][4];
            // pass 1 operands
            #pragma unroll
            for (int mt = 0; mt < 2; mt++) {
                uint32_t o = swz((uint32_t)((a_r + mt * 16) * 128 + (a_c8 + kc) * 2));
                LDSM_X4(ah[mt][0], ah[mt][1], ah[mt][2], ah[mt][3], a_hi_base + o);
            }
            #pragma unroll
            for (int np = 0; np < 2; np++) {
                uint32_t o = swz((uint32_t)((b_r + np * 16) * 128 + (b_c8 + kc) * 2));
                LDSM_X4(fh[np][0], fh[np][1], fh[np][2], fh[np][3], b_hi_base + o);
            }
            // pass 1: hh  (8 independent MMAs)
            #pragma unroll
            for (int mt = 0; mt < 2; mt++)
                #pragma unroll
                for (int nt = 0; nt < 4; nt++) {
                    float* c = acc[mt][nt];
                    MMA_BF16(c[0], c[1], c[2], c[3],
                             ah[mt][0], ah[mt][1], ah[mt][2], ah[mt][3],
                             fh[nt >> 1][(nt & 1) * 2], fh[nt >> 1][(nt & 1) * 2 + 1]);
                }
            // pass 2 operand (A lo)
            #pragma unroll
            for (int mt = 0; mt < 2; mt++) {
                uint32_t o = swz((uint32_t)((a_r + mt * 16) * 128 + (a_c8 + kc) * 2));
                LDSM_X4(al[mt][0], al[mt][1], al[mt][2], al[mt][3], a_lo_base + o);
            }
            // pass 2: lh
            #pragma unroll
            for (int mt = 0; mt < 2; mt++)
                #pragma unroll
                for (int nt = 0; nt < 4; nt++) {
                    float* c = acc[mt][nt];
                    MMA_BF16(c[0], c[1], c[2], c[3],
                             al[mt][0], al[mt][1], al[mt][2], al[mt][3],
                             fh[nt >> 1][(nt & 1) * 2], fh[nt >> 1][(nt & 1) * 2 + 1]);
                }
            // pass 3 operand (B lo)
            #pragma unroll
            for (int np = 0; np < 2; np++) {
                uint32_t o = swz((uint32_t)((b_r + np * 16) * 128 + (b_c8 + kc) * 2));
                LDSM_X4(fl[np][0], fl[np][1], fl[np][2], fl[np][3], b_lo_base + o);
            }
            // pass 3: hl
            #pragma unroll
            for (int mt = 0; mt < 2; mt++)
                #pragma unroll
                for (int nt = 0; nt < 4; nt++) {
                    float* c = acc[mt][nt];
                    MMA_BF16(c[0], c[1], c[2], c[3],
                             ah[mt][0], ah[mt][1], ah[mt][2], ah[mt][3],
                             fl[nt >> 1][(nt & 1) * 2], fl[nt >> 1][(nt & 1) * 2 + 1]);
                }
        }

        // ---- epilogue on tile boundary (register-only + __ldg) --------------
        if (dc == 3) {
            const int nbase = tile * NTILE;
            #pragma unroll
            for (int mt = 0; mt < 2; mt++)
                #pragma unroll
                for (int half = 0; half < 2; half++) {
                    const int slot = mt * 2 + half;
                    #pragma unroll
                    for (int nt = 0; nt < 4; nt++) {
                        const int coll = wn * 32 + nt * 8 + (lane & 3) * 2;
                        #pragma unroll
                        for (int p = 0; p < 2; p++) {
                            float cq = __ldg(&g_cbsq[nbase + coll + p]);
                            float d  = cq - 2.0f * acc[mt][nt][half * 2 + p];
                            int gi = nbase + coll + p;
                            if (d < t1d[slot] || (d == t1d[slot] && gi < t1i[slot])) {
                                t2d[slot] = t1d[slot]; t1d[slot] = d; t1i[slot] = gi;
                            } else if (d < t2d[slot]) {
                                t2d[slot] = d;
                            }
                        }
                    }
                }
            #pragma unroll
            for (int mt = 0; mt < 2; mt++)
                #pragma unroll
                for (int nt = 0; nt < 4; nt++)
                    #pragma unroll
                    for (int p = 0; p < 4; p++)
                        acc[mt][nt][p] = 0.f;
        }
    }

    // ---- final merge: overlay reduction arrays on the B region -------------
    __syncthreads();
    float* rd1 = (float*)(smem + SM_B);
    int*   ri1 = (int*)(smem + SM_B + 2048);
    float* rd2 = (float*)(smem + SM_B + 4096);

    #pragma unroll
    for (int slot = 0; slot < 4; slot++) {
        float d1 = t1d[slot], d2 = t2d[slot];
        int   i1 = t1i[slot];
        #pragma unroll
        for (int off = 1; off <= 2; off <<= 1) {
            float od1 = __shfl_xor_sync(0xffffffffu, d1, off);
            int   oi1 = __shfl_xor_sync(0xffffffffu, i1, off);
            float od2 = __shfl_xor_sync(0xffffffffu, d2, off);
            if (od1 < d1 || (od1 == d1 && oi1 < i1)) {
                d2 = fminf(d1, od2); d1 = od1; i1 = oi1;
            } else {
                d2 = fminf(d2, od1);
            }
        }
        if ((lane & 3) == 0) {
            int row = wm * 32 + (slot >> 1) * 16 + (slot & 1) * 8 + (lane >> 2);
            rd1[row * 4 + wn] = d1;
            ri1[row * 4 + wn] = i1;
            rd2[row * 4 + wn] = d2;
        }
    }
    __syncthreads();

    if (tid < MT) {
        float d1 = rd1[tid * 4], d2 = rd2[tid * 4];
        int   i1 = ri1[tid * 4];
        #pragma unroll
        for (int w = 1; w < 4; w++) {
            float od1 = rd1[tid * 4 + w], od2 = rd2[tid * 4 + w];
            int   oi1 = ri1[tid * 4 + w];
            if (od1 < d1 || (od1 == d1 && oi1 < i1)) {
                d2 = fminf(d1, od2); d1 = od1; i1 = oi1;
            } else {
                d2 = fminf(d2, od1);
            }
        }
        out[qbase + tid]   = (float)i1;
        g_gap[qbase + tid] = d2 - d1;
    }
}

// ---------------------------------------------------------------------------
// Rescue: exact fp32 re-scan, one 256-thread block per query; early exit.
// ---------------------------------------------------------------------------
__global__ void rescue_kernel(const float* __restrict__ z,
                              const float* __restrict__ cb,
                              float* __restrict__ out) {
    const int q = blockIdx.x;
    if (g_gap[q] >= EPS) return;
    const int tid  = threadIdx.x;
    const int wid  = tid >> 5;
    const int lane = tid & 31;

    __shared__ float swd[8];
    __shared__ int   swi[8];

    float zr[8];
    #pragma unroll
    for (int i = 0; i < 8; i++) zr[i] = z[(size_t)q * DD + lane + i * 32];

    float bd = INFINITY;
    int   bi = 0x7fffffff;
    const int n0 = wid * (KC / 8);
    #pragma unroll 2
    for (int k = 0; k < KC / 8; k++) {
        const int n = n0 + k;
        const float* cr = cb + (size_t)n * DD;
        float dot = 0.f;
        #pragma unroll
        for (int i = 0; i < 8; i++) dot = fmaf(zr[i], cr[lane + i * 32], dot);
        #pragma unroll
        for (int off = 16; off; off >>= 1) dot += __shfl_xor_sync(0xffffffffu, dot, off);
        float dist = g_cbsq[n] - 2.0f * dot;
        if (dist < bd) { bd = dist; bi = n; }
    }
    if (lane == 0) { swd[wid] = bd; swi[wid] = bi; }
    __syncthreads();
    if (tid == 0) {
        float d = swd[0]; int i1 = swi[0];
        #pragma unroll
        for (int w = 1; w < 8; w++) {
            if (swd[w] < d || (swd[w] == d && swi[w] < i1)) { d = swd[w]; i1 = swi[w]; }
        }
        out[q] = (float)i1;
    }
}

// ---------------------------------------------------------------------------
extern "C" void kernel_launch(void* const* d_in, const int* in_sizes, int n_in,
                              void* d_out, int out_size) {
    // z_e_x is always the larger buffer (4x codebook).
    const float* z;
    const float* cb;
    if (in_sizes[0] >= in_sizes[1]) { z = (const float*)d_in[0]; cb = (const float*)d_in[1]; }
    else                            { cb = (const float*)d_in[0]; z = (const float*)d_in[1]; }
    float* out = (float*)d_out;

    cudaFuncSetAttribute(vq_mma_kernel,
                         cudaFuncAttributeMaxDynamicSharedMemorySize, SM_TOTAL);

    prep_kernel<<<KC / 8, 256>>>(cb);
    vq_mma_kernel<<<NQ / MT, 512, SM_TOTAL>>>(z, out);
    rescue_kernel<<<NQ, 256>>>(z, cb, out);
}

// round 9
// speedup vs baseline: 1.0579x; 1.0579x over previous
#include <cuda_runtime.h>
#include <cuda_bf16.h>
#include <cstdint>
#include <math.h>

#define NQ      32768
#define KC      8192
#define DD      256
#define MT      128           // queries per CTA
#define NTILE   128           // codes per tile
#define NTILES  (KC / NTILE)  // 64
#define NSTAGES (NTILES * 4)  // 256 (64-dim chunks)
#define WTH     1.5e-4f       // crowd window (>= 2x worst coarse dist error)

// ---------------- device scratch (no cudaMalloc) ----------------------------
__device__ float         g_cbsq[KC];
__device__ __nv_bfloat16 g_cb_hi[KC * DD];
__device__ int4          g_cand[NQ];
__device__ int           g_crowd[NQ];

// ---------------- smem layout (bytes) ---------------------------------------
// A: 4 dc-chunks x (128 x 64 bf16 SW128) = 64KB (hi only)
// B: 3 stages x 16KB (hi only) = 48KB
// merge overlay reuses the A region after the mainloop.
#define SM_A     0
#define SM_B     65536
#define SM_TOTAL 114688        // 112 KB

__device__ __forceinline__ uint32_t smem_u32(const void* p) {
    uint32_t a;
    asm("{ .reg .u64 t; cvta.to.shared.u64 t, %1; cvt.u32.u64 %0, t; }"
        : "=r"(a) : "l"(p));
    return a;
}
__device__ __forceinline__ uint32_t swz(uint32_t b) { return b ^ ((b >> 3) & 0x70); }

#define LDSM_X4(r0, r1, r2, r3, addr) \
    asm volatile("ldmatrix.sync.aligned.m8n8.x4.shared.b16 {%0,%1,%2,%3}, [%4];" \
                 : "=r"(r0), "=r"(r1), "=r"(r2), "=r"(r3) : "r"(addr))

#define MMA_BF16(c0, c1, c2, c3, a0, a1, a2, a3, b0, b1) \
    asm volatile("mma.sync.aligned.m16n8k16.row.col.f32.bf16.bf16.f32 " \
                 "{%0,%1,%2,%3}, {%4,%5,%6,%7}, {%8,%9}, {%0,%1,%2,%3};" \
                 : "+f"(c0), "+f"(c1), "+f"(c2), "+f"(c3) \
                 : "r"(a0), "r"(a1), "r"(a2), "r"(a3), "r"(b0), "r"(b1))

#define CP16(dst, src) \
    asm volatile("cp.async.cg.shared.global [%0], [%1], 16;" :: "r"(dst), "l"(src))
#define CP_COMMIT() asm volatile("cp.async.commit_group;" ::: "memory")
#define CP_WAIT(n)  asm volatile("cp.async.wait_group %0;" :: "n"(n) : "memory")

// ---------------------------------------------------------------------------
// Prep: codebook -> bf16 hi + ||e||^2. One warp per code.
// ---------------------------------------------------------------------------
__global__ void prep_kernel(const float* __restrict__ cb) {
    int w = (blockIdx.x * blockDim.x + threadIdx.x) >> 5;
    int lane = threadIdx.x & 31;
    if (w >= KC) return;
    const float4* row = (const float4*)(cb + (size_t)w * DD);
    float s = 0.f;
    #pragma unroll
    for (int i = 0; i < 2; i++) {
        int f = lane + i * 32;
        float4 v = row[f];
        s += v.x * v.x + v.y * v.y + v.z * v.z + v.w * v.w;
        __nv_bfloat162 h0 = {__float2bfloat16_rn(v.x), __float2bfloat16_rn(v.y)};
        __nv_bfloat162 h1 = {__float2bfloat16_rn(v.z), __float2bfloat16_rn(v.w)};
        uint2 hu = {*(uint32_t*)&h0, *(uint32_t*)&h1};
        *(uint2*)(g_cb_hi + (size_t)w * DD + f * 4) = hu;
    }
    #pragma unroll
    for (int off = 16; off; off >>= 1) s += __shfl_xor_sync(0xffffffffu, s, off);
    if (lane == 0) g_cbsq[w] = s;
}

// ---------------------------------------------------------------------------
// Main: single-pass bf16 HMMA + fused per-thread top-4.
// 512 threads = 16 warps (4M x 4N). CTA: 128 queries x all 8192 codes.
// ---------------------------------------------------------------------------
__global__ void __launch_bounds__(512, 1)
vq_mma_kernel(const float* __restrict__ z) {
    extern __shared__ char smem[];
    const uint32_t sb = smem_u32(smem);
    const int tid  = threadIdx.x;
    const int wid  = tid >> 5;
    const int lane = tid & 31;
    const int wm   = wid >> 2;     // 0..3
    const int wn   = wid & 3;      // 0..3
    const int qbase = blockIdx.x * MT;

    // per-thread cp.async components (1024 chunks of 16B per stage, 2/thread)
    const int cp_row0 = tid >> 3;
    const int cp_row1 = (tid + 512) >> 3;
    const int cp_c8   = (tid & 7) * 8;
    const uint32_t cp_o0 = swz((uint32_t)(cp_row0 * 128 + cp_c8 * 2));
    const uint32_t cp_o1 = swz((uint32_t)(cp_row1 * 128 + cp_c8 * 2));

    // prologue: issue B stages 0,1
    #pragma unroll
    for (int s = 0; s < 2; s++) {
        const uint32_t bst = sb + SM_B + s * 16384;
        const int tile = s >> 2, dc = s & 3;
        size_t src0 = (size_t)(tile * NTILE + cp_row0) * DD + dc * 64 + cp_c8;
        size_t src1 = (size_t)(tile * NTILE + cp_row1) * DD + dc * 64 + cp_c8;
        CP16(bst + cp_o0, g_cb_hi + src0);
        CP16(bst + cp_o1, g_cb_hi + src1);
        CP_COMMIT();
    }

    // convert z tile (128x256 fp32) to swizzled bf16-hi chunks
    #pragma unroll
    for (int i = 0; i < 16; i++) {
        int id  = tid + i * 512;
        int row = id >> 6;
        int col = (id & 63) * 4;
        int dc  = col >> 6;
        int cl  = col & 63;
        float4 v = *(const float4*)(z + (size_t)(qbase + row) * DD + col);
        __nv_bfloat162 h0 = {__float2bfloat16_rn(v.x), __float2bfloat16_rn(v.y)};
        __nv_bfloat162 h1 = {__float2bfloat16_rn(v.z), __float2bfloat16_rn(v.w)};
        uint2 hu = {*(uint32_t*)&h0, *(uint32_t*)&h1};
        uint32_t o = (uint32_t)(dc * 16384) + swz((uint32_t)(row * 128 + cl * 2));
        *(uint2*)(smem + SM_A + o) = hu;
    }

    const int a_r  = wm * 32 + (lane & 15);
    const int a_c8 = (lane >> 4) * 8;
    const int b_r  = wn * 32 + (lane & 7) + ((lane >> 4) & 1) * 8;
    const int b_c8 = ((lane >> 3) & 1) * 8;

    // per-thread top-4 per row-slot, sorted ascending by (d, idx)
    float td[4][4];
    int   ti[4][4];
    #pragma unroll
    for (int s = 0; s < 4; s++)
        #pragma unroll
        for (int e = 0; e < 4; e++) { td[s][e] = INFINITY; ti[s][e] = 0x7fffffff; }

    float acc[2][4][4] = {};

    #pragma unroll 1
    for (int s = 0; s < NSTAGES; s++) {
        const int tile = s >> 2;
        const int dc   = s & 3;
        const uint32_t buf = sb + SM_B + (uint32_t)(s % 3) * 16384;

        if (s + 1 < NSTAGES) { CP_WAIT(1); } else { CP_WAIT(0); }
        __syncthreads();

        if (s + 2 < NSTAGES) {
            const int nt_ = (s + 2) >> 2, ndc = (s + 2) & 3;
            const uint32_t bst = sb + SM_B + (uint32_t)((s + 2) % 3) * 16384;
            size_t src0 = (size_t)(nt_ * NTILE + cp_row0) * DD + ndc * 64 + cp_c8;
            size_t src1 = (size_t)(nt_ * NTILE + cp_row1) * DD + ndc * 64 + cp_c8;
            CP16(bst + cp_o0, g_cb_hi + src0);
            CP16(bst + cp_o1, g_cb_hi + src1);
            CP_COMMIT();
        }

        const uint32_t a_base = sb + SM_A + dc * 16384;

        #pragma unroll
        for (int k16 = 0; k16 < 4; k16++) {
            const int kc = k16 * 16;
            uint32_t ah[2][4], fh[2][4];
            #pragma unroll
            for (int mt = 0; mt < 2; mt++) {
                uint32_t o = swz((uint32_t)((a_r + mt * 16) * 128 + (a_c8 + kc) * 2));
                LDSM_X4(ah[mt][0], ah[mt][1], ah[mt][2], ah[mt][3], a_base + o);
            }
            #pragma unroll
            for (int np = 0; np < 2; np++) {
                uint32_t o = swz((uint32_t)((b_r + np * 16) * 128 + (b_c8 + kc) * 2));
                LDSM_X4(fh[np][0], fh[np][1], fh[np][2], fh[np][3], buf + o);
            }
            #pragma unroll
            for (int mt = 0; mt < 2; mt++)
                #pragma unroll
                for (int nt = 0; nt < 4; nt++) {
                    float* c = acc[mt][nt];
                    MMA_BF16(c[0], c[1], c[2], c[3],
                             ah[mt][0], ah[mt][1], ah[mt][2], ah[mt][3],
                             fh[nt >> 1][(nt & 1) * 2], fh[nt >> 1][(nt & 1) * 2 + 1]);
                }
        }

        // ---- epilogue on tile boundary: top-4 insertion ---------------------
        if (dc == 3) {
            const int nbase = tile * NTILE;
            #pragma unroll
            for (int mt = 0; mt < 2; mt++)
                #pragma unroll
                for (int half = 0; half < 2; half++) {
                    const int slot = mt * 2 + half;
                    #pragma unroll
                    for (int nt = 0; nt < 4; nt++) {
                        const int coll = wn * 32 + nt * 8 + (lane & 3) * 2;
                        #pragma unroll
                        for (int p = 0; p < 2; p++) {
                            float cq = __ldg(&g_cbsq[nbase + coll + p]);
                            float d  = cq - 2.0f * acc[mt][nt][half * 2 + p];
                            int gi = nbase + coll + p;
                            if (d < td[slot][3] ||
                                (d == td[slot][3] && gi < ti[slot][3])) {
                                td[slot][3] = d; ti[slot][3] = gi;
                                #pragma unroll
                                for (int j = 2; j >= 0; j--) {
                                    if (td[slot][j + 1] < td[slot][j] ||
                                        (td[slot][j + 1] == td[slot][j] &&
                                         ti[slot][j + 1] < ti[slot][j])) {
                                        float tdd = td[slot][j]; td[slot][j] = td[slot][j + 1]; td[slot][j + 1] = tdd;
                                        int   tii = ti[slot][j]; ti[slot][j] = ti[slot][j + 1]; ti[slot][j + 1] = tii;
                                    }
                                }
                            }
                        }
                    }
                }
            #pragma unroll
            for (int mt = 0; mt < 2; mt++)
                #pragma unroll
                for (int nt = 0; nt < 4; nt++)
                    #pragma unroll
                    for (int p = 0; p < 4; p++)
                        acc[mt][nt][p] = 0.f;
        }
    }

    // ---- merge via smem overlay on the A region -----------------------------
    __syncthreads();
    float* rd = (float*)(smem);            // [128 q][16 slots][4]
    int*   ri = (int*)(smem + 32768);      // [128 q][16 slots][4]

    #pragma unroll
    for (int slot = 0; slot < 4; slot++) {
        int row  = wm * 32 + (slot >> 1) * 16 + (slot & 1) * 8 + (lane >> 2);
        int sidx = wn * 4 + (lane & 3);
        #pragma unroll
        for (int e = 0; e < 4; e++) {
            rd[(row * 16 + sidx) * 4 + e] = td[slot][e];
            ri[(row * 16 + sidx) * 4 + e] = ti[slot][e];
        }
    }
    __syncthreads();

    if (tid < MT) {
        float bd[4]; int bi[4];
        #pragma unroll
        for (int e = 0; e < 4; e++) { bd[e] = INFINITY; bi[e] = 0x7fffffff; }
        #pragma unroll 4
        for (int e = 0; e < 64; e++) {
            float d = rd[tid * 64 + e];
            int   i = ri[tid * 64 + e];
            if (d < bd[3] || (d == bd[3] && i < bi[3])) {
                bd[3] = d; bi[3] = i;
                #pragma unroll
                for (int j = 2; j >= 0; j--) {
                    if (bd[j + 1] < bd[j] || (bd[j + 1] == bd[j] && bi[j + 1] < bi[j])) {
                        float tdd = bd[j]; bd[j] = bd[j + 1]; bd[j + 1] = tdd;
                        int   tii = bi[j]; bi[j] = bi[j + 1]; bi[j + 1] = tii;
                    }
                }
            }
        }
        const int q = qbase + tid;
        g_cand[q]  = make_int4(bi[0], bi[1], bi[2], bi[3]);
        g_crowd[q] = (bd[3] - bd[0] < WTH) ? 1 : 0;
    }
}

// ---------------------------------------------------------------------------
// Recheck: exact fp32 distance for the 4 candidates; one warp per query.
// ---------------------------------------------------------------------------
__global__ void recheck_kernel(const float* __restrict__ z,
                               const float* __restrict__ cb,
                               float* __restrict__ out) {
    int q = (blockIdx.x * blockDim.x + threadIdx.x) >> 5;
    if (q >= NQ) return;
    int lane = threadIdx.x & 31;

    float zr[8];
    #pragma unroll
    for (int i = 0; i < 8; i++) zr[i] = z[(size_t)q * DD + lane + i * 32];

    int4 cd = g_cand[q];
    int cands[4] = {cd.x, cd.y, cd.z, cd.w};

    float bd = INFINITY;
    int   bi = 0x7fffffff;
    #pragma unroll
    for (int c = 0; c < 4; c++) {
        int n = cands[c];
        const float* cr = cb + (size_t)n * DD;
        float dot = 0.f;
        #pragma unroll
        for (int i = 0; i < 8; i++) dot = fmaf(zr[i], cr[lane + i * 32], dot);
        #pragma unroll
        for (int off = 16; off; off >>= 1) dot += __shfl_xor_sync(0xffffffffu, dot, off);
        float dist = g_cbsq[n] - 2.0f * dot;
        if (dist < bd || (dist == bd && n < bi)) { bd = dist; bi = n; }
    }
    if (lane == 0) out[q] = (float)bi;
}

// ---------------------------------------------------------------------------
// Fallback: exact fp32 full scan for crowded queries; 256-thread block/query.
// ---------------------------------------------------------------------------
__global__ void fallback_kernel(const float* __restrict__ z,
                                const float* __restrict__ cb,
                                float* __restrict__ out) {
    const int q = blockIdx.x;
    if (!g_crowd[q]) return;
    const int tid  = threadIdx.x;
    const int wid  = tid >> 5;
    const int lane = tid & 31;

    __shared__ float swd[8];
    __shared__ int   swi[8];

    float zr[8];
    #pragma unroll
    for (int i = 0; i < 8; i++) zr[i] = z[(size_t)q * DD + lane + i * 32];

    float bd = INFINITY;
    int   bi = 0x7fffffff;
    const int n0 = wid * (KC / 8);
    #pragma unroll 2
    for (int k = 0; k < KC / 8; k++) {
        const int n = n0 + k;
        const float* cr = cb + (size_t)n * DD;
        float dot = 0.f;
        #pragma unroll
        for (int i = 0; i < 8; i++) dot = fmaf(zr[i], cr[lane + i * 32], dot);
        #pragma unroll
        for (int off = 16; off; off >>= 1) dot += __shfl_xor_sync(0xffffffffu, dot, off);
        float dist = g_cbsq[n] - 2.0f * dot;
        if (dist < bd) { bd = dist; bi = n; }
    }
    if (lane == 0) { swd[wid] = bd; swi[wid] = bi; }
    __syncthreads();
    if (tid == 0) {
        float d = swd[0]; int i1 = swi[0];
        #pragma unroll
        for (int w = 1; w < 8; w++) {
            if (swd[w] < d || (swd[w] == d && swi[w] < i1)) { d = swd[w]; i1 = swi[w]; }
        }
        out[q] = (float)i1;
    }
}

// ---------------------------------------------------------------------------
extern "C" void kernel_launch(void* const* d_in, const int* in_sizes, int n_in,
                              void* d_out, int out_size) {
    // z_e_x is always the larger buffer (4x codebook).
    const float* z;
    const float* cb;
    if (in_sizes[0] >= in_sizes[1]) { z = (const float*)d_in[0]; cb = (const float*)d_in[1]; }
    else                            { cb = (const float*)d_in[0]; z = (const float*)d_in[1]; }
    float* out = (float*)d_out;

    cudaFuncSetAttribute(vq_mma_kernel,
                         cudaFuncAttributeMaxDynamicSharedMemorySize, SM_TOTAL);

    prep_kernel<<<KC / 8, 256>>>(cb);
    vq_mma_kernel<<<NQ / MT, 512, SM_TOTAL>>>(z);
    recheck_kernel<<<NQ / 8, 256>>>(z, cb, out);
    fallback_kernel<<<NQ, 256>>>(z, cb, out);
}